// round 2
// baseline (speedup 1.0000x reference)
#include <cuda_runtime.h>
#include <math.h>

#define Bn 32
#define Tn 256
#define OBS 32
#define LAT 64
#define HID 400
#define P 65                      // smem pitch: 65 floats -> conflict-free rows AND cols
#define L2PI 1.8378770664093453f  // ln(2*pi)

#define XR_OFF 0
#define LL_OFF (Bn*Tn*OBS)                    // 262144
#define MQ_OFF (LL_OFF + Bn)                  // 262176
#define SQ_OFF (MQ_OFF + Bn*Tn*LAT)           // 786464

// ---------------- device scratch (no cudaMalloc allowed) ----------------
__device__ float g_Q[LAT*LAT];
__device__ float g_zmu[Bn*Tn*LAT];
__device__ float g_sig[Bn*Tn*LAT];
__device__ float g_mf [Bn*Tn*LAT];
__device__ float g_Sf [(size_t)Bn*Tn*LAT*LAT];   // 134 MB

// ---------------- 64x64 matmul helpers (require blockDim.x == 256) ------
// Thread map: tx = tid&15, ty = tid>>4. rows r0..r0+3 (r0=4*ty), cols tx+16*j.
// Row loads broadcast (2 addrs/warp); col loads hit 16 distinct consecutive
// addresses (conflict-free with pitch 65).

__device__ __forceinline__ void mm_AB_plus(float* C, const float* A, const float* Bm, const float* Add) {
    int tx = threadIdx.x & 15, ty = threadIdx.x >> 4;
    int r0 = ty * 4;
    float acc[4][4];
#pragma unroll
    for (int i = 0; i < 4; i++)
#pragma unroll
        for (int j = 0; j < 4; j++) acc[i][j] = 0.f;
#pragma unroll 4
    for (int k = 0; k < 64; k++) {
        float a0 = A[(r0+0)*P+k], a1 = A[(r0+1)*P+k], a2 = A[(r0+2)*P+k], a3 = A[(r0+3)*P+k];
        float b0 = Bm[k*P+tx], b1 = Bm[k*P+tx+16], b2 = Bm[k*P+tx+32], b3 = Bm[k*P+tx+48];
        acc[0][0] += a0*b0; acc[0][1] += a0*b1; acc[0][2] += a0*b2; acc[0][3] += a0*b3;
        acc[1][0] += a1*b0; acc[1][1] += a1*b1; acc[1][2] += a1*b2; acc[1][3] += a1*b3;
        acc[2][0] += a2*b0; acc[2][1] += a2*b1; acc[2][2] += a2*b2; acc[2][3] += a2*b3;
        acc[3][0] += a3*b0; acc[3][1] += a3*b1; acc[3][2] += a3*b2; acc[3][3] += a3*b3;
    }
#pragma unroll
    for (int i = 0; i < 4; i++)
#pragma unroll
        for (int j = 0; j < 4; j++) {
            int idx = (r0+i)*P + tx + 16*j;
            C[idx] = Add ? (acc[i][j] + Add[idx]) : acc[i][j];
        }
}

// C = Add - A@B   (M1 = Sp - K@Sp)
__device__ __forceinline__ void mm_sub(float* C, const float* A, const float* Bm, const float* Add) {
    int tx = threadIdx.x & 15, ty = threadIdx.x >> 4;
    int r0 = ty * 4;
    float acc[4][4];
#pragma unroll
    for (int i = 0; i < 4; i++)
#pragma unroll
        for (int j = 0; j < 4; j++) acc[i][j] = 0.f;
#pragma unroll 4
    for (int k = 0; k < 64; k++) {
        float a0 = A[(r0+0)*P+k], a1 = A[(r0+1)*P+k], a2 = A[(r0+2)*P+k], a3 = A[(r0+3)*P+k];
        float b0 = Bm[k*P+tx], b1 = Bm[k*P+tx+16], b2 = Bm[k*P+tx+32], b3 = Bm[k*P+tx+48];
        acc[0][0] += a0*b0; acc[0][1] += a0*b1; acc[0][2] += a0*b2; acc[0][3] += a0*b3;
        acc[1][0] += a1*b0; acc[1][1] += a1*b1; acc[1][2] += a1*b2; acc[1][3] += a1*b3;
        acc[2][0] += a2*b0; acc[2][1] += a2*b1; acc[2][2] += a2*b2; acc[2][3] += a2*b3;
        acc[3][0] += a3*b0; acc[3][1] += a3*b1; acc[3][2] += a3*b2; acc[3][3] += a3*b3;
    }
#pragma unroll
    for (int i = 0; i < 4; i++)
#pragma unroll
        for (int j = 0; j < 4; j++) {
            int idx = (r0+i)*P + tx + 16*j;
            C[idx] = Add[idx] - acc[i][j];
        }
}

// C = Add + A @ B^T
__device__ __forceinline__ void mm_ABt_plus(float* C, const float* A, const float* Bm, const float* Add) {
    int tx = threadIdx.x & 15, ty = threadIdx.x >> 4;
    int r0 = ty * 4;
    float acc[4][4];
#pragma unroll
    for (int i = 0; i < 4; i++)
#pragma unroll
        for (int j = 0; j < 4; j++) acc[i][j] = 0.f;
#pragma unroll 4
    for (int k = 0; k < 64; k++) {
        float a0 = A[(r0+0)*P+k], a1 = A[(r0+1)*P+k], a2 = A[(r0+2)*P+k], a3 = A[(r0+3)*P+k];
        float b0 = Bm[(tx   )*P+k], b1 = Bm[(tx+16)*P+k], b2 = Bm[(tx+32)*P+k], b3 = Bm[(tx+48)*P+k];
        acc[0][0] += a0*b0; acc[0][1] += a0*b1; acc[0][2] += a0*b2; acc[0][3] += a0*b3;
        acc[1][0] += a1*b0; acc[1][1] += a1*b1; acc[1][2] += a1*b2; acc[1][3] += a1*b3;
        acc[2][0] += a2*b0; acc[2][1] += a2*b1; acc[2][2] += a2*b2; acc[2][3] += a2*b3;
        acc[3][0] += a3*b0; acc[3][1] += a3*b1; acc[3][2] += a3*b2; acc[3][3] += a3*b3;
    }
#pragma unroll
    for (int i = 0; i < 4; i++)
#pragma unroll
        for (int j = 0; j < 4; j++) {
            int idx = (r0+i)*P + tx + 16*j;
            C[idx] = acc[i][j] + Add[idx];
        }
}

// C = A @ (X - Y)
__device__ __forceinline__ void mm_A_diff(float* C, const float* A, const float* X, const float* Y) {
    int tx = threadIdx.x & 15, ty = threadIdx.x >> 4;
    int r0 = ty * 4;
    float acc[4][4];
#pragma unroll
    for (int i = 0; i < 4; i++)
#pragma unroll
        for (int j = 0; j < 4; j++) acc[i][j] = 0.f;
#pragma unroll 4
    for (int k = 0; k < 64; k++) {
        float a0 = A[(r0+0)*P+k], a1 = A[(r0+1)*P+k], a2 = A[(r0+2)*P+k], a3 = A[(r0+3)*P+k];
        float b0 = X[k*P+tx   ] - Y[k*P+tx   ];
        float b1 = X[k*P+tx+16] - Y[k*P+tx+16];
        float b2 = X[k*P+tx+32] - Y[k*P+tx+32];
        float b3 = X[k*P+tx+48] - Y[k*P+tx+48];
        acc[0][0] += a0*b0; acc[0][1] += a0*b1; acc[0][2] += a0*b2; acc[0][3] += a0*b3;
        acc[1][0] += a1*b0; acc[1][1] += a1*b1; acc[1][2] += a1*b2; acc[1][3] += a1*b3;
        acc[2][0] += a2*b0; acc[2][1] += a2*b1; acc[2][2] += a2*b2; acc[2][3] += a2*b3;
        acc[3][0] += a3*b0; acc[3][1] += a3*b1; acc[3][2] += a3*b2; acc[3][3] += a3*b3;
    }
#pragma unroll
    for (int i = 0; i < 4; i++)
#pragma unroll
        for (int j = 0; j < 4; j++)
            C[(r0+i)*P + tx + 16*j] = acc[i][j];
}

// Joseph form fused: C = M1 - M1 K^T + K diag(rd) K^T
//   C[i][j] = M1[i][j] + sum_k (K[i][k]*rd[k] - M1[i][k]) * K[j][k]
__device__ __forceinline__ void jos64(float* C, const float* M1, const float* K, const float* rd) {
    int tx = threadIdx.x & 15, ty = threadIdx.x >> 4;
    int r0 = ty * 4;
    float acc[4][4];
#pragma unroll
    for (int i = 0; i < 4; i++)
#pragma unroll
        for (int j = 0; j < 4; j++) acc[i][j] = 0.f;
#pragma unroll 2
    for (int k = 0; k < 64; k++) {
        float rk = rd[k];
        float t0 = K[(r0+0)*P+k]*rk - M1[(r0+0)*P+k];
        float t1 = K[(r0+1)*P+k]*rk - M1[(r0+1)*P+k];
        float t2 = K[(r0+2)*P+k]*rk - M1[(r0+2)*P+k];
        float t3 = K[(r0+3)*P+k]*rk - M1[(r0+3)*P+k];
        float b0 = K[(tx   )*P+k], b1 = K[(tx+16)*P+k], b2 = K[(tx+32)*P+k], b3 = K[(tx+48)*P+k];
        acc[0][0] += t0*b0; acc[0][1] += t0*b1; acc[0][2] += t0*b2; acc[0][3] += t0*b3;
        acc[1][0] += t1*b0; acc[1][1] += t1*b1; acc[1][2] += t1*b2; acc[1][3] += t1*b3;
        acc[2][0] += t2*b0; acc[2][1] += t2*b1; acc[2][2] += t2*b2; acc[2][3] += t2*b3;
        acc[3][0] += t3*b0; acc[3][1] += t3*b1; acc[3][2] += t3*b2; acc[3][3] += t3*b3;
    }
#pragma unroll
    for (int i = 0; i < 4; i++)
#pragma unroll
        for (int j = 0; j < 4; j++) {
            int idx = (r0+i)*P + tx + 16*j;
            C[idx] = M1[idx] + acc[i][j];
        }
}

// ---------------- Cholesky 64x64 in shared (LDL'-scaled trick) ----------
// In-place on lower triangle of M (pitch P). Produces proper L in the lower
// triangle (incl. diag), plus dvec[i]=L[i][i] and invd[i]=1/L[i][i].
// 2 barriers per column. blockDim-agnostic. Uniform control flow required.
__device__ void chol64(float* M, float* dvec, float* invd) {
    const int tid = threadIdx.x;
    const int nt  = blockDim.x;
    for (int k = 0; k < 64; k++) {
        __syncthreads();
        if (tid == 0) {
            float d = sqrtf(M[k*P+k]);
            dvec[k] = d;
            invd[k] = 1.0f / d;
        }
        __syncthreads();
        float iv  = invd[k];
        float iv2 = iv * iv;
        for (int idx = tid; idx < 4096; idx += nt) {
            int i = idx >> 6, j = idx & 63;
            if (i > k && j > k && j <= i)
                M[i*P+j] -= M[i*P+k] * M[j*P+k] * iv2;
        }
    }
    __syncthreads();
    for (int idx = tid; idx < 4096; idx += nt) {
        int i = idx >> 6, j = idx & 63;
        if (j < i)       M[i*P+j] *= invd[j];
        else if (j == i) M[i*P+i]  = dvec[i];
    }
    __syncthreads();
}

// ---------------- column-parallel cho_solve --------------------------
// Threads 0..63: solve L Y = RHS[:,c] then L^T X = Y, write KT[c][i]=X[i][c].
// Y may alias RHS (in-place). Thread 64 (optional): forward-solve rvec into
// column 64 of Y and emit ||alpha||^2. No internal barriers.
__device__ void cho_solve64(const float* L, const float* invd, const float* RHS,
                            float* Y, float* KT, const float* rvec, float* alpha2_out) {
    int c = threadIdx.x;
    if (c < 64) {
        for (int i = 0; i < 64; i++) {
            float acc0 = RHS[i*P + c], acc1 = 0.f;
            int j = 0;
            for (; j + 1 < i; j += 2) {
                acc0 -= L[i*P+j]     * Y[j*P+c];
                acc1 += L[i*P+j+1]   * Y[(j+1)*P+c];
            }
            if (j < i) acc0 -= L[i*P+j] * Y[j*P+c];
            Y[i*P+c] = (acc0 - acc1) * invd[i];
        }
        for (int i = 63; i >= 0; i--) {
            float acc0 = Y[i*P+c], acc1 = 0.f;
            int j = i + 1;
            for (; j + 1 < 64; j += 2) {
                acc0 -= L[j*P+i]     * Y[j*P+c];
                acc1 += L[(j+1)*P+i] * Y[(j+1)*P+c];
            }
            if (j < 64) acc0 -= L[j*P+i] * Y[j*P+c];
            float xv = (acc0 - acc1) * invd[i];
            Y[i*P+c]    = xv;
            KT[c*P + i] = xv;
        }
    } else if (c == 64 && rvec != nullptr) {
        for (int i = 0; i < 64; i++) {
            float acc = rvec[i];
            for (int j = 0; j < i; j++) acc -= L[i*P+j] * Y[j*P+64];
            Y[i*P+64] = acc * invd[i];
        }
        float s = 0.f;
        for (int i = 0; i < 64; i++) { float a = Y[i*P+64]; s += a*a; }
        *alpha2_out = s;
    }
}

// ========================== kernels ====================================

__global__ void k_buildQ(const float* __restrict__ qp) {
    __shared__ float sL[LAT*P];
    int tid = threadIdx.x;
    for (int idx = tid; idx < LAT*LAT; idx += blockDim.x) {
        int i = idx >> 6, j = idx & 63;
        float v = 0.f;
        if (j <= i) { v = qp[i*(i+1)/2 + j]; if (j == i) v = expf(v); }
        sL[i*P+j] = v;
    }
    __syncthreads();
    for (int idx = tid; idx < LAT*LAT; idx += blockDim.x) {
        int i = idx >> 6, j = idx & 63;
        int m = i < j ? i : j;
        float acc = 0.f;
        for (int k = 0; k <= m; k++) acc += sL[i*P+k] * sL[j*P+k];
        g_Q[idx] = acc;
    }
}

__global__ void k_encoder(const float* __restrict__ x,
                          const float* __restrict__ W1, const float* __restrict__ b1,
                          const float* __restrict__ Wm, const float* __restrict__ bm,
                          const float* __restrict__ Wl, const float* __restrict__ bl) {
    __shared__ float xs[OBS];
    __shared__ float h[HID];
    int tok = blockIdx.x, tid = threadIdx.x;
    if (tid < OBS) xs[tid] = x[tok*OBS + tid];
    __syncthreads();
    for (int j = tid; j < HID; j += blockDim.x) {
        float acc = b1[j];
#pragma unroll
        for (int k = 0; k < OBS; k++) acc += xs[k] * W1[k*HID + j];
        h[j] = fmaxf(acc, 0.f);
    }
    __syncthreads();
    if (tid < LAT) {
        float acc = bm[tid];
        for (int j = 0; j < HID; j++) acc += h[j] * Wm[j*LAT + tid];
        g_zmu[tok*LAT + tid] = acc;
    } else if (tid < 2*LAT) {
        int o = tid - LAT;
        float acc = bl[o];
        for (int j = 0; j < HID; j++) acc += h[j] * Wl[j*LAT + o];
        g_sig[tok*LAT + o] = expf(0.5f * acc);
    }
}

__global__ void __launch_bounds__(256, 1)
k_filter(const float* __restrict__ Amat, const float* __restrict__ bvec_g,
         const int* __restrict__ mask, float* __restrict__ out_ll) {
    extern __shared__ float sm[];
    float* sA   = sm;
    float* sAT  = sA   + LAT*P;
    float* sQ   = sAT  + LAT*P;
    float* sSig = sQ   + LAT*P;
    float* sT1  = sSig + LAT*P;
    float* sSp  = sT1  + LAT*P;
    float* sS   = sSp  + LAT*P;
    float* sK   = sS   + LAT*P;
    float* vb   = sK   + LAT*P;
    float* mu   = vb;        float* mup  = mu   + 64;
    float* muu  = mup + 64;  float* r    = muu  + 64;
    float* rd   = r   + 64;  float* bv   = rd   + 64;
    float* dvec = bv  + 64;  float* invd = dvec + 64;
    float* scal = invd + 64;  // [0]=alpha2 [1]=sumlog [2]=ll

    int b = blockIdx.x, tid = threadIdx.x;

    for (int idx = tid; idx < LAT*LAT; idx += 256) {
        int i = idx >> 6, j = idx & 63;
        float a = Amat[idx];
        sA [i*P+j] = a;
        sAT[j*P+i] = a;
        sQ [i*P+j] = g_Q[idx];
        sSig[i*P+j] = (i == j) ? 1.f : 0.f;
    }
    if (tid < 64) { mu[tid] = 0.f; bv[tid] = bvec_g[tid]; }
    if (tid == 0) scal[2] = 0.f;
    __syncthreads();

    for (int t = 0; t < Tn; t++) {
        int base = (b*Tn + t) * LAT;
        int m = mask[b*Tn + t];

        if (tid < 64) {
            float acc = bv[tid];
            for (int k = 0; k < 64; k++) acc += sA[tid*P+k] * mu[k];
            mup[tid] = acc;
            r[tid]   = g_zmu[base + tid] - acc;
            rd[tid]  = g_sig[base + tid];
        }
        __syncthreads();

        mm_AB_plus(sT1, sA, sSig, nullptr);          // T1 = A @ Sig
        __syncthreads();
        mm_AB_plus(sSp, sT1, sAT, sQ);               // Sp = T1 @ A^T + Q
        __syncthreads();

        if (m) {
            if (tid < 64) mu[tid] = mup[tid];
            for (int idx = tid; idx < LAT*LAT; idx += 256) {
                int i = idx >> 6, j = idx & 63;
                sSig[i*P+j] = sSp[i*P+j];
            }
        } else {
            for (int idx = tid; idx < LAT*LAT; idx += 256) {
                int i = idx >> 6, j = idx & 63;
                sS[i*P+j] = sSp[i*P+j] + ((i == j) ? rd[i] : 0.f);
            }
            chol64(sS, dvec, invd);                  // L in sS
            cho_solve64(sS, invd, sSp, sT1, sK, r, &scal[0]);  // K = (S^-1 Sp)^T
            if (tid == 65) {
                float s = 0.f;
                for (int i = 0; i < 64; i++) s += logf(dvec[i]);
                scal[1] = s;
            }
            __syncthreads();

            if (tid < 64) {
                float acc = mup[tid];
                for (int k = 0; k < 64; k++) acc += sK[tid*P+k] * r[k];
                muu[tid] = acc;
            }
            mm_sub(sT1, sK, sSp, sSp);               // M1 = Sp - K@Sp = (I-K)Sp
            __syncthreads();
            jos64(sSig, sT1, sK, rd);                // Sig = M1(I-K)^T + K R K^T
            if (tid < 64) mu[tid] = muu[tid];
            if (tid == 0)
                scal[2] += -0.5f * 64.f * L2PI - scal[1] - 0.5f * scal[0];
        }
        __syncthreads();

        if (tid < 64) g_mf[base + tid] = mu[tid];
        for (int idx = tid; idx < LAT*LAT; idx += 256)
            g_Sf[(size_t)base * 64 + idx] = sSig[(idx >> 6)*P + (idx & 63)];
        __syncthreads();
    }
    if (tid == 0) out_ll[b] = scal[2];
}

__global__ void __launch_bounds__(256, 1)
k_smoother(const float* __restrict__ Amat, const float* __restrict__ bvec_g,
           float* __restrict__ out) {
    extern __shared__ float sm[];
    float* sA   = sm;
    float* sAT  = sA   + LAT*P;
    float* sQ   = sAT  + LAT*P;
    float* sSf  = sQ   + LAT*P;
    float* sSs  = sSf  + LAT*P;
    float* sT1  = sSs  + LAT*P;
    float* sSp  = sT1  + LAT*P;
    float* sS   = sSp  + LAT*P;
    float* sG   = sS   + LAT*P;
    float* vb   = sG   + LAT*P;
    float* mfv    = vb;          float* mus  = mfv    + 64;
    float* mupred = mus  + 64;   float* dm   = mupred + 64;
    float* nmu    = dm   + 64;   float* bv   = nmu    + 64;
    float* dvec   = bv   + 64;   float* invd = dvec   + 64;

    int b = blockIdx.x, tid = threadIdx.x;
    float* out_mq = out + MQ_OFF;
    float* out_sq = out + SQ_OFF;

    for (int idx = tid; idx < LAT*LAT; idx += 256) {
        int i = idx >> 6, j = idx & 63;
        float a = Amat[idx];
        sA [i*P+j] = a;
        sAT[j*P+i] = a;
        sQ [i*P+j] = g_Q[idx];
    }
    size_t baseT = ((size_t)b*Tn + (Tn-1)) * LAT;
    if (tid < 64) {
        mus[tid] = g_mf[baseT + tid];
        bv[tid]  = bvec_g[tid];
        out_mq[baseT + tid] = mus[tid];
    }
    for (int idx = tid; idx < LAT*LAT; idx += 256) {
        float v = g_Sf[baseT*64 + idx];
        sSs[(idx >> 6)*P + (idx & 63)] = v;
        out_sq[baseT*64 + idx] = v;
    }
    __syncthreads();

    for (int t = Tn - 2; t >= 0; t--) {
        size_t base = ((size_t)b*Tn + t) * LAT;
        if (tid < 64) mfv[tid] = g_mf[base + tid];
        for (int idx = tid; idx < LAT*LAT; idx += 256)
            sSf[(idx >> 6)*P + (idx & 63)] = g_Sf[base*64 + idx];
        __syncthreads();

        if (tid < 64) {
            float acc = bv[tid];
            for (int k = 0; k < 64; k++) acc += sA[tid*P+k] * mfv[k];
            mupred[tid] = acc;
            dm[tid] = mus[tid] - acc;
        }
        __syncthreads();

        mm_AB_plus(sT1, sA, sSf, nullptr);           // T1 = A @ Sf
        __syncthreads();
        mm_AB_plus(sSp, sT1, sAT, sQ);               // Spred = T1 @ A^T + Q
        __syncthreads();
        for (int idx = tid; idx < LAT*LAT; idx += 256) {
            int i = idx >> 6, j = idx & 63;
            sS[i*P+j] = sSp[i*P+j];
        }
        chol64(sS, dvec, invd);
        cho_solve64(sS, invd, sT1, sT1, sG, nullptr, nullptr);  // G = (Spred^-1 T1)^T
        __syncthreads();

        if (tid < 64) {
            float acc = mfv[tid];
            for (int k = 0; k < 64; k++) acc += sG[tid*P+k] * dm[k];
            nmu[tid] = acc;
        }
        mm_A_diff(sT1, sG, sSs, sSp);                // M1 = G @ (Ss - Spred)
        __syncthreads();
        mm_ABt_plus(sSs, sT1, sG, sSf);              // Ss = Sf + M1 @ G^T
        if (tid < 64) mus[tid] = nmu[tid];
        __syncthreads();

        if (tid < 64) out_mq[base + tid] = mus[tid];
        for (int idx = tid; idx < LAT*LAT; idx += 256)
            out_sq[base*64 + idx] = sSs[(idx >> 6)*P + (idx & 63)];
        __syncthreads();
    }
}

__global__ void k_sample(const float* __restrict__ eps,
                         const float* __restrict__ Wd, const float* __restrict__ bd,
                         float* __restrict__ out) {
    __shared__ float sM[LAT*P];
    __shared__ float ev[64], zv[64], dvec[64], invd[64];
    int tok = blockIdx.x, tid = threadIdx.x;
    const float* sq = out + SQ_OFF + (size_t)tok * (LAT*LAT);
    const float* mq = out + MQ_OFF + tok * LAT;

    for (int idx = tid; idx < LAT*LAT; idx += blockDim.x) {
        int i = idx >> 6, j = idx & 63;
        sM[i*P+j] = sq[idx] + ((i == j) ? 1e-5f : 0.f);
    }
    if (tid < 64) ev[tid] = eps[tok*LAT + tid];
    chol64(sM, dvec, invd);   // internal leading barrier covers the loads

    if (tid < 64) {
        float acc = mq[tid];
        for (int j = 0; j <= tid; j++) acc += sM[tid*P+j] * ev[j];  // diag == dvec
        zv[tid] = acc;
    }
    __syncthreads();
    if (tid < OBS) {
        float acc = bd[tid];
        for (int i = 0; i < 64; i++) acc += zv[i] * Wd[i*OBS + tid];
        out[XR_OFF + tok*OBS + tid] = acc;
    }
}

// ========================== launch ====================================

extern "C" void kernel_launch(void* const* d_in, const int* in_sizes, int n_in,
                              void* d_out, int out_size) {
    const float* x    = (const float*)d_in[0];
    const int*   mask = (const int*)  d_in[1];
    const float* eps  = (const float*)d_in[2];
    const float* W1   = (const float*)d_in[3];
    const float* b1   = (const float*)d_in[4];
    const float* Wm   = (const float*)d_in[5];
    const float* bm   = (const float*)d_in[6];
    const float* Wl   = (const float*)d_in[7];
    const float* bl   = (const float*)d_in[8];
    const float* Wd   = (const float*)d_in[9];
    const float* bd   = (const float*)d_in[10];
    const float* A    = (const float*)d_in[11];
    const float* bvec = (const float*)d_in[12];
    const float* Qp   = (const float*)d_in[13];
    float* out = (float*)d_out;

    k_buildQ <<<1, 256>>>(Qp);
    k_encoder<<<Bn*Tn, 128>>>(x, W1, b1, Wm, bm, Wl, bl);

    size_t smemF = (size_t)(8*LAT*P + 9*64 + 16) * sizeof(float);   // ~135.5 KB
    cudaFuncSetAttribute(k_filter, cudaFuncAttributeMaxDynamicSharedMemorySize, (int)smemF);
    k_filter<<<Bn, 256, smemF>>>(A, bvec, mask, out + LL_OFF);

    size_t smemS = (size_t)(9*LAT*P + 8*64 + 16) * sizeof(float);   // ~152 KB
    cudaFuncSetAttribute(k_smoother, cudaFuncAttributeMaxDynamicSharedMemorySize, (int)smemS);
    k_smoother<<<Bn, 256, smemS>>>(A, bvec, out);

    k_sample<<<Bn*Tn, 128>>>(eps, Wd, bd, out);
}